// round 1
// baseline (speedup 1.0000x reference)
#include <cuda_runtime.h>

// Problem constants
#define NB      8
#define SQ      1024
#define DIN     1280
#define RNK     64
#define DOUT    1280
#define DOWNSZ  (RNK * DIN)          // 81920
#define UPSZ    (DOUT * RNK)         // 81920
#define EMBSZ   (DOWNSZ + UPSZ)      // 163840

typedef unsigned long long u64;

// Intermediate h[B][S][RANK] — device global (no allocations allowed)
__device__ float g_h[NB * SQ * RNK];

// ---- packed fp32x2 helpers (sm_100+ PTX; ptxas never emits these itself) ----
__device__ __forceinline__ u64 pk2(float a, float b) {
    u64 r; asm("mov.b64 %0, {%1,%2};" : "=l"(r) : "f"(a), "f"(b)); return r;
}
__device__ __forceinline__ u64 bc2(float a) {
    u64 r; asm("mov.b64 %0, {%1,%1};" : "=l"(r) : "f"(a)); return r;
}
__device__ __forceinline__ void up2(u64 v, float& a, float& b) {
    asm("mov.b64 {%0,%1}, %2;" : "=f"(a), "=f"(b) : "l"(v));
}
__device__ __forceinline__ void fma2(u64& d, u64 a, u64 b) {
    asm("fma.rn.f32x2 %0, %1, %2, %0;" : "+l"(d) : "l"(a), "l"(b));
}

// ============================================================================
// Kernel 1: h[b,s,r] = sum_d x[b,s,d] * w_down[b,r,d]
// GEMM per b: M=1024(s), N=64(r), K=1280(d). Block tile 64x64, BK=16,
// double-buffered smem, 256 threads, thread tile 4s x 4r (f32x2 pairs on r).
// grid = (S/64, B) = (16, 8)
// ============================================================================
__global__ __launch_bounds__(256, 2)
void k_down(const float* __restrict__ x, const float* __restrict__ embed) {
    __shared__ float xs[2][16][68];   // [buf][k][s]  (+4 pad)
    __shared__ float ws[2][16][68];   // [buf][k][r]

    const int b  = blockIdx.y;
    const int s0 = blockIdx.x * 64;
    const float* __restrict__ xb = x     + ((size_t)b * SQ + s0) * DIN;
    const float* __restrict__ wd = embed + (size_t)b * EMBSZ;       // [RNK][DIN]

    const int tid = threadIdx.x;
    const int lr  = tid >> 2;          // load row 0..63
    const int c4  = (tid & 3) * 4;     // load col 0..12 (within 16-wide chunk)
    const int tx  = tid & 15;          // r-group (4 cols each)
    const int ty  = tid >> 4;          // s-group (4 rows each)

    u64 acc[4][2];
#pragma unroll
    for (int i = 0; i < 4; i++) { acc[i][0] = 0ull; acc[i][1] = 0ull; }

    // prolog: load chunk 0 into buffer 0
    float4 xv = *(const float4*)(xb + (size_t)lr * DIN + c4);
    float4 wv = *(const float4*)(wd + (size_t)lr * DIN + c4);
    xs[0][c4 + 0][lr] = xv.x; xs[0][c4 + 1][lr] = xv.y;
    xs[0][c4 + 2][lr] = xv.z; xs[0][c4 + 3][lr] = xv.w;
    ws[0][c4 + 0][lr] = wv.x; ws[0][c4 + 1][lr] = wv.y;
    ws[0][c4 + 2][lr] = wv.z; ws[0][c4 + 3][lr] = wv.w;
    __syncthreads();

    const int NCH = DIN / 16;          // 80 chunks
    for (int k = 0; k < NCH; k++) {
        const int cur = k & 1;
        if (k + 1 < NCH) {             // prefetch next chunk to registers
            const int k0 = (k + 1) * 16;
            xv = *(const float4*)(xb + (size_t)lr * DIN + k0 + c4);
            wv = *(const float4*)(wd + (size_t)lr * DIN + k0 + c4);
        }
#pragma unroll
        for (int kk = 0; kk < 16; kk++) {
            float4 xr = *(const float4*)&xs[cur][kk][ty * 4];
            float4 wr = *(const float4*)&ws[cur][kk][tx * 4];
            u64 wp0 = pk2(wr.x, wr.y), wp1 = pk2(wr.z, wr.w);
            u64 b0 = bc2(xr.x), b1 = bc2(xr.y), b2 = bc2(xr.z), b3 = bc2(xr.w);
            fma2(acc[0][0], b0, wp0); fma2(acc[0][1], b0, wp1);
            fma2(acc[1][0], b1, wp0); fma2(acc[1][1], b1, wp1);
            fma2(acc[2][0], b2, wp0); fma2(acc[2][1], b2, wp1);
            fma2(acc[3][0], b3, wp0); fma2(acc[3][1], b3, wp1);
        }
        if (k + 1 < NCH) {             // store prefetched chunk to other buffer
            const int nxt = cur ^ 1;
            xs[nxt][c4 + 0][lr] = xv.x; xs[nxt][c4 + 1][lr] = xv.y;
            xs[nxt][c4 + 2][lr] = xv.z; xs[nxt][c4 + 3][lr] = xv.w;
            ws[nxt][c4 + 0][lr] = wv.x; ws[nxt][c4 + 1][lr] = wv.y;
            ws[nxt][c4 + 2][lr] = wv.z; ws[nxt][c4 + 3][lr] = wv.w;
            __syncthreads();
        }
    }

    float* hp = g_h + ((size_t)b * SQ + s0) * RNK;
#pragma unroll
    for (int i = 0; i < 4; i++) {
        float a0, a1, a2, a3;
        up2(acc[i][0], a0, a1); up2(acc[i][1], a2, a3);
        float4 o; o.x = a0; o.y = a1; o.z = a2; o.w = a3;
        *(float4*)(hp + (size_t)(ty * 4 + i) * RNK + tx * 4) = o;
    }
}

// ============================================================================
// Kernel 2: out[b,s,o] = sum_r h[b,s,r] * w_up[b,o,r]
// GEMM per b: M=1024(s), N=1280(o), K=64(r). Full K in smem, block tile 64x64,
// 256 threads, thread tile 4s x 4o.   grid = (S/64, DOUT/64, B) = (16, 20, 8)
// ============================================================================
__global__ __launch_bounds__(256, 2)
void k_up(const float* __restrict__ embed, float* __restrict__ out) {
    __shared__ float hs[64][68];   // [r][s]
    __shared__ float wu[64][68];   // [r][o]

    const int b  = blockIdx.z;
    const int s0 = blockIdx.x * 64;
    const int o0 = blockIdx.y * 64;
    const float* __restrict__ hp = g_h + ((size_t)b * SQ + s0) * RNK;
    const float* __restrict__ wp = embed + (size_t)b * EMBSZ + DOWNSZ
                                   + (size_t)o0 * RNK;     // [64 o][64 r]

    const int tid = threadIdx.x;
    const int lr  = tid >> 2;          // row 0..63
    const int c4  = (tid & 3) * 4;     // 0..12

    // Load full 64x64 h tile and 64x64 w_up tile (transposed to [r][row])
#pragma unroll
    for (int e = 0; e < 4; e++) {
        const int c = e * 16 + c4;     // r index 0..63
        float4 hv = *(const float4*)(hp + (size_t)lr * RNK + c);
        float4 wv = *(const float4*)(wp + (size_t)lr * RNK + c);
        hs[c + 0][lr] = hv.x; hs[c + 1][lr] = hv.y;
        hs[c + 2][lr] = hv.z; hs[c + 3][lr] = hv.w;
        wu[c + 0][lr] = wv.x; wu[c + 1][lr] = wv.y;
        wu[c + 2][lr] = wv.z; wu[c + 3][lr] = wv.w;
    }
    __syncthreads();

    const int tx = tid & 15;           // o-group
    const int ty = tid >> 4;           // s-group
    u64 acc[4][2];
#pragma unroll
    for (int i = 0; i < 4; i++) { acc[i][0] = 0ull; acc[i][1] = 0ull; }

#pragma unroll
    for (int kk = 0; kk < 64; kk++) {
        float4 xr = *(const float4*)&hs[kk][ty * 4];
        float4 wr = *(const float4*)&wu[kk][tx * 4];
        u64 wp0 = pk2(wr.x, wr.y), wp1 = pk2(wr.z, wr.w);
        u64 b0 = bc2(xr.x), b1 = bc2(xr.y), b2 = bc2(xr.z), b3 = bc2(xr.w);
        fma2(acc[0][0], b0, wp0); fma2(acc[0][1], b0, wp1);
        fma2(acc[1][0], b1, wp0); fma2(acc[1][1], b1, wp1);
        fma2(acc[2][0], b2, wp0); fma2(acc[2][1], b2, wp1);
        fma2(acc[3][0], b3, wp0); fma2(acc[3][1], b3, wp1);
    }

    float* op = out + ((size_t)b * SQ + s0) * DOUT + o0;
#pragma unroll
    for (int i = 0; i < 4; i++) {
        float a0, a1, a2, a3;
        up2(acc[i][0], a0, a1); up2(acc[i][1], a2, a3);
        float4 o; o.x = a0; o.y = a1; o.z = a2; o.w = a3;
        *(float4*)(op + (size_t)(ty * 4 + i) * DOUT + tx * 4) = o;
    }
}

extern "C" void kernel_launch(void* const* d_in, const int* in_sizes, int n_in,
                              void* d_out, int out_size) {
    const float* x     = (const float*)d_in[0];   // [8,1024,1280] fp32
    const float* embed = (const float*)d_in[1];   // [8,163840]    fp32
    float*       out   = (float*)d_out;           // [8,1024,1280] fp32
    (void)in_sizes; (void)n_in; (void)out_size;

    k_down<<<dim3(16, 8), 256>>>(x, embed);
    k_up<<<dim3(16, 20, 8), 256>>>(embed, out);
}

// round 2
// speedup vs baseline: 1.1694x; 1.1694x over previous
#include <cuda_runtime.h>

#define NB      8
#define SQ      1024
#define DIN     1280
#define RNK     64
#define DOUT    1280
#define DOWNSZ  (RNK * DIN)
#define UPSZ    (DOUT * RNK)
#define EMBSZ   (DOWNSZ + UPSZ)
#define KCH     640                  // K-chunk for split-K down

typedef unsigned long long u64;

// split-K partials for h  (no device allocations allowed)
__device__ float g_hp[2][NB * SQ * RNK];

// ---- packed fp32x2 helpers ----
__device__ __forceinline__ u64 pk2(float a, float b) {
    u64 r; asm("mov.b64 %0, {%1,%2};" : "=l"(r) : "f"(a), "f"(b)); return r;
}
__device__ __forceinline__ u64 bc2(float a) {
    u64 r; asm("mov.b64 %0, {%1,%1};" : "=l"(r) : "f"(a)); return r;
}
__device__ __forceinline__ void up2(u64 v, float& a, float& b) {
    asm("mov.b64 {%0,%1}, %2;" : "=f"(a), "=f"(b) : "l"(v));
}
__device__ __forceinline__ void fma2(u64& d, u64 a, u64 b) {
    asm("fma.rn.f32x2 %0, %1, %2, %0;" : "+l"(d) : "l"(a), "l"(b));
}

// ============================================================================
// k_down: h_partial[kc][b,s,r] = sum_{d in chunk kc} x[b,s,d] * w_down[b,r,d]
// Block tile 128(s) x 64(r), K-chunk 640, BK=16 double-buffered.
// 128 threads, thread tile 8x8 (fragments at {ty*4, 64+ty*4} x {tx*4, 32+tx*4})
// grid = (8 s-tiles, 2 k-chunks, 8 b)
// ============================================================================
__global__ __launch_bounds__(128)
void k_down(const float* __restrict__ x, const float* __restrict__ embed) {
    __shared__ float xs[2][16][132];   // [buf][k][s]
    __shared__ float ws[2][16][68];    // [buf][k][r]

    const int b  = blockIdx.z;
    const int kc = blockIdx.y;
    const int s0 = blockIdx.x * 128;
    const float* __restrict__ xb = x     + ((size_t)b * SQ + s0) * DIN + kc * KCH;
    const float* __restrict__ wd = embed + (size_t)b * EMBSZ + kc * KCH;  // [r][DIN]

    const int tid = threadIdx.x;
    const int lr  = tid >> 2;            // 0..31
    const int c4  = (tid & 3) * 4;       // 0,4,8,12
    const int tx  = tid & 7;             // r-group
    const int ty  = tid >> 3;            // s-group 0..15

    u64 acc[8][4];
#pragma unroll
    for (int i = 0; i < 8; i++)
#pragma unroll
        for (int j = 0; j < 4; j++) acc[i][j] = 0ull;

    float4 xv[4], wv[2];

    // prolog: chunk 0 -> buf 0
#pragma unroll
    for (int e = 0; e < 4; e++)
        xv[e] = *(const float4*)(xb + (size_t)(lr + e * 32) * DIN + c4);
#pragma unroll
    for (int e = 0; e < 2; e++)
        wv[e] = *(const float4*)(wd + (size_t)(lr + e * 32) * DIN + c4);
#pragma unroll
    for (int e = 0; e < 4; e++) {
        xs[0][c4 + 0][lr + e * 32] = xv[e].x; xs[0][c4 + 1][lr + e * 32] = xv[e].y;
        xs[0][c4 + 2][lr + e * 32] = xv[e].z; xs[0][c4 + 3][lr + e * 32] = xv[e].w;
    }
#pragma unroll
    for (int e = 0; e < 2; e++) {
        ws[0][c4 + 0][lr + e * 32] = wv[e].x; ws[0][c4 + 1][lr + e * 32] = wv[e].y;
        ws[0][c4 + 2][lr + e * 32] = wv[e].z; ws[0][c4 + 3][lr + e * 32] = wv[e].w;
    }
    __syncthreads();

    const int NCH = KCH / 16;            // 40
    for (int k = 0; k < NCH; k++) {
        const int cur = k & 1;
        if (k + 1 < NCH) {
            const int k0 = (k + 1) * 16;
#pragma unroll
            for (int e = 0; e < 4; e++)
                xv[e] = *(const float4*)(xb + (size_t)(lr + e * 32) * DIN + k0 + c4);
#pragma unroll
            for (int e = 0; e < 2; e++)
                wv[e] = *(const float4*)(wd + (size_t)(lr + e * 32) * DIN + k0 + c4);
        }
#pragma unroll
        for (int kk = 0; kk < 16; kk++) {
            float4 x0 = *(const float4*)&xs[cur][kk][ty * 4];
            float4 x1 = *(const float4*)&xs[cur][kk][64 + ty * 4];
            float4 w0 = *(const float4*)&ws[cur][kk][tx * 4];
            float4 w1 = *(const float4*)&ws[cur][kk][32 + tx * 4];
            u64 wp0 = pk2(w0.x, w0.y), wp1 = pk2(w0.z, w0.w);
            u64 wp2 = pk2(w1.x, w1.y), wp3 = pk2(w1.z, w1.w);
            u64 bv[8] = { bc2(x0.x), bc2(x0.y), bc2(x0.z), bc2(x0.w),
                          bc2(x1.x), bc2(x1.y), bc2(x1.z), bc2(x1.w) };
#pragma unroll
            for (int i = 0; i < 8; i++) {
                fma2(acc[i][0], bv[i], wp0); fma2(acc[i][1], bv[i], wp1);
                fma2(acc[i][2], bv[i], wp2); fma2(acc[i][3], bv[i], wp3);
            }
        }
        if (k + 1 < NCH) {
            const int nxt = cur ^ 1;
#pragma unroll
            for (int e = 0; e < 4; e++) {
                xs[nxt][c4 + 0][lr + e * 32] = xv[e].x; xs[nxt][c4 + 1][lr + e * 32] = xv[e].y;
                xs[nxt][c4 + 2][lr + e * 32] = xv[e].z; xs[nxt][c4 + 3][lr + e * 32] = xv[e].w;
            }
#pragma unroll
            for (int e = 0; e < 2; e++) {
                ws[nxt][c4 + 0][lr + e * 32] = wv[e].x; ws[nxt][c4 + 1][lr + e * 32] = wv[e].y;
                ws[nxt][c4 + 2][lr + e * 32] = wv[e].z; ws[nxt][c4 + 3][lr + e * 32] = wv[e].w;
            }
            __syncthreads();
        }
    }

    float* hp = g_hp[kc] + ((size_t)b * SQ + s0) * RNK;
#pragma unroll
    for (int e = 0; e < 2; e++)
#pragma unroll
        for (int i = 0; i < 4; i++) {
            const int row = e * 64 + ty * 4 + i;
            const int ai  = e * 4 + i;
            float a0, a1, a2, a3;
            up2(acc[ai][0], a0, a1); up2(acc[ai][1], a2, a3);
            float4 o0; o0.x = a0; o0.y = a1; o0.z = a2; o0.w = a3;
            *(float4*)(hp + (size_t)row * RNK + tx * 4) = o0;
            up2(acc[ai][2], a0, a1); up2(acc[ai][3], a2, a3);
            float4 o1; o1.x = a0; o1.y = a1; o1.z = a2; o1.w = a3;
            *(float4*)(hp + (size_t)row * RNK + 32 + tx * 4) = o1;
        }
}

// ============================================================================
// k_up: out[b,s,o] = sum_r (hp0+hp1)[b,s,r] * w_up[b,o,r]
// Block tile 128(s) x 128(o), K=64 in two 32-wide smem phases.
// 256 threads, thread tile 8x8 (fragments at {ty*4, 64+ty*4} x {tx*4, 64+tx*4})
// grid = (8, 10, 8)
// ============================================================================
__global__ __launch_bounds__(256)
void k_up(const float* __restrict__ embed, float* __restrict__ out) {
    __shared__ float hs[32][132];   // [r][s]
    __shared__ float wu[32][132];   // [r][o]

    const int b  = blockIdx.z;
    const int s0 = blockIdx.x * 128;
    const int o0 = blockIdx.y * 128;
    const float* __restrict__ h0 = g_hp[0] + ((size_t)b * SQ + s0) * RNK;
    const float* __restrict__ h1 = g_hp[1] + ((size_t)b * SQ + s0) * RNK;
    const float* __restrict__ wp = embed + (size_t)b * EMBSZ + DOWNSZ
                                   + (size_t)o0 * RNK;          // [o][r]

    const int tid = threadIdx.x;
    const int lr  = tid >> 2;            // 0..63
    const int c4  = (tid & 3) * 4;       // 0,4,8,12
    const int tx  = tid & 15;            // o-group
    const int ty  = tid >> 4;            // s-group

    u64 acc[8][4];
#pragma unroll
    for (int i = 0; i < 8; i++)
#pragma unroll
        for (int j = 0; j < 4; j++) acc[i][j] = 0ull;

#pragma unroll
    for (int ph = 0; ph < 2; ph++) {
        // fill: 32 k-cols (r = ph*32 + lk) for 128 rows of h (summed partials) and w_up
#pragma unroll
        for (int e = 0; e < 2; e++) {
            const int row = lr + e * 64;
#pragma unroll
            for (int f = 0; f < 2; f++) {
                const int lk = c4 + f * 16;           // 0..31 within phase
                const int c  = ph * 32 + lk;          // global r
                float4 ha = *(const float4*)(h0 + (size_t)row * RNK + c);
                float4 hb = *(const float4*)(h1 + (size_t)row * RNK + c);
                float4 wv = *(const float4*)(wp + (size_t)row * RNK + c);
                hs[lk + 0][row] = ha.x + hb.x; hs[lk + 1][row] = ha.y + hb.y;
                hs[lk + 2][row] = ha.z + hb.z; hs[lk + 3][row] = ha.w + hb.w;
                wu[lk + 0][row] = wv.x; wu[lk + 1][row] = wv.y;
                wu[lk + 2][row] = wv.z; wu[lk + 3][row] = wv.w;
            }
        }
        __syncthreads();

#pragma unroll
        for (int kk = 0; kk < 32; kk++) {
            float4 x0 = *(const float4*)&hs[kk][ty * 4];
            float4 x1 = *(const float4*)&hs[kk][64 + ty * 4];
            float4 w0 = *(const float4*)&wu[kk][tx * 4];
            float4 w1 = *(const float4*)&wu[kk][64 + tx * 4];
            u64 wp0 = pk2(w0.x, w0.y), wp1 = pk2(w0.z, w0.w);
            u64 wp2 = pk2(w1.x, w1.y), wp3 = pk2(w1.z, w1.w);
            u64 bv[8] = { bc2(x0.x), bc2(x0.y), bc2(x0.z), bc2(x0.w),
                          bc2(x1.x), bc2(x1.y), bc2(x1.z), bc2(x1.w) };
#pragma unroll
            for (int i = 0; i < 8; i++) {
                fma2(acc[i][0], bv[i], wp0); fma2(acc[i][1], bv[i], wp1);
                fma2(acc[i][2], bv[i], wp2); fma2(acc[i][3], bv[i], wp3);
            }
        }
        __syncthreads();
    }

    float* op = out + ((size_t)b * SQ + s0) * DOUT + o0;
#pragma unroll
    for (int e = 0; e < 2; e++)
#pragma unroll
        for (int i = 0; i < 4; i++) {
            const int row = e * 64 + ty * 4 + i;
            const int ai  = e * 4 + i;
            float a0, a1, a2, a3;
            up2(acc[ai][0], a0, a1); up2(acc[ai][1], a2, a3);
            float4 q0; q0.x = a0; q0.y = a1; q0.z = a2; q0.w = a3;
            *(float4*)(op + (size_t)row * DOUT + tx * 4) = q0;
            up2(acc[ai][2], a0, a1); up2(acc[ai][3], a2, a3);
            float4 q1; q1.x = a0; q1.y = a1; q1.z = a2; q1.w = a3;
            *(float4*)(op + (size_t)row * DOUT + 64 + tx * 4) = q1;
        }
}

extern "C" void kernel_launch(void* const* d_in, const int* in_sizes, int n_in,
                              void* d_out, int out_size) {
    const float* x     = (const float*)d_in[0];   // [8,1024,1280]
    const float* embed = (const float*)d_in[1];   // [8,163840]
    float*       out   = (float*)d_out;           // [8,1024,1280]
    (void)in_sizes; (void)n_in; (void)out_size;

    k_down<<<dim3(8, 2, 8), 128>>>(x, embed);
    k_up<<<dim3(8, 10, 8), 256>>>(embed, out);
}

// round 5
// speedup vs baseline: 1.5874x; 1.3575x over previous
#include <cuda_runtime.h>
#include <cuda_bf16.h>
#include <cstdint>

#define NB 8
#define SQ 1024
#define DIN 1280
#define RNK 64
#define DOUT 1280
#define DOWNSZ (RNK*DIN)
#define UPSZ (DOUT*RNK)
#define EMBSZ (DOWNSZ+UPSZ)

#define LDP 72   // padded K stride in bf16 elems (conflict-free frag loads)

// intermediate h as bf16 hi/lo split pair
__device__ __nv_bfloat16 g_hh[NB*SQ*RNK];
__device__ __nv_bfloat16 g_hl[NB*SQ*RNK];

// fp32 pair -> packed bf16 hi pair + bf16 residual pair
__device__ __forceinline__ void split2(float a, float b, uint32_t& hi, uint32_t& lo) {
    __nv_bfloat16 ha = __float2bfloat16_rn(a), hb = __float2bfloat16_rn(b);
    float ra = a - __bfloat162float(ha), rb = b - __bfloat162float(hb);
    __nv_bfloat162 H; H.x = ha; H.y = hb;
    __nv_bfloat162 L; L.x = __float2bfloat16_rn(ra); L.y = __float2bfloat16_rn(rb);
    hi = *reinterpret_cast<uint32_t*>(&H);
    lo = *reinterpret_cast<uint32_t*>(&L);
}

// m16n8k16 row.col bf16 -> f32 accumulate (baseline PTX, legacy HMMA pipe)
__device__ __forceinline__ void mma16816(float* d, const uint32_t* a, const uint32_t* b) {
    asm volatile("mma.sync.aligned.m16n8k16.row.col.f32.bf16.bf16.f32 "
        "{%0,%1,%2,%3}, {%4,%5,%6,%7}, {%8,%9}, {%0,%1,%2,%3};"
        : "+f"(d[0]), "+f"(d[1]), "+f"(d[2]), "+f"(d[3])
        : "r"(a[0]), "r"(a[1]), "r"(a[2]), "r"(a[3]), "r"(b[0]), "r"(b[1]));
}

// ============================================================================
// k_down: h[b,s,r] = sum_d x[b,s,d] * w_down[b,r,d]
// tile 64(s) x 64(r); K in 20 chunks of 64; smem double-buffered, reg prefetch.
// 256 thr = 8 warps (4m x 2n), warp tile 16x32 -> 1 m-tile x 4 n-tiles.
// grid (16 s-tiles, 8 b) = 128 CTAs.
// ============================================================================
static constexpr int D_T   = 64 * LDP;          // elems per tile
static constexpr int D_BUF = 4 * D_T;           // AH AL WH WL
static constexpr int SMEM_DOWN = 2 * D_BUF * 2; // bytes = 73728

__global__ __launch_bounds__(256)
void k_down(const float* __restrict__ x, const float* __restrict__ embed) {
    extern __shared__ __nv_bfloat16 sm[];
    const int tid = threadIdx.x, lane = tid & 31, wid = tid >> 5;
    const int b = blockIdx.y, s0 = blockIdx.x * 64;
    const float* __restrict__ xb = x + ((size_t)b * SQ + s0) * DIN;
    const float* __restrict__ wd = embed + (size_t)b * EMBSZ;   // [RNK][DIN]

    const int frow = tid >> 4;          // 0..15
    const int fcol = (tid & 15) * 4;    // 0..60
    const int wm = wid >> 1, wn = wid & 1;
    const int m0 = wm * 16, n0 = wn * 32;
    const int g = lane >> 2, tg = lane & 3;

    float acc[4][4];
#pragma unroll
    for (int u = 0; u < 4; u++)
#pragma unroll
        for (int j = 0; j < 4; j++) acc[u][j] = 0.f;

    // fill buffer 0 (chunk 0)
    {
        __nv_bfloat16* AH = sm;          __nv_bfloat16* AL = sm + D_T;
        __nv_bfloat16* WH = sm + 2*D_T;  __nv_bfloat16* WL = sm + 3*D_T;
#pragma unroll
        for (int p = 0; p < 4; p++) {
            const int row = p * 16 + frow;
            float4 xv = *(const float4*)(xb + (size_t)row * DIN + fcol);
            float4 wv = *(const float4*)(wd + (size_t)row * DIN + fcol);
            uint32_t h0, l0, h1, l1;
            split2(xv.x, xv.y, h0, l0); split2(xv.z, xv.w, h1, l1);
            *(uint2*)(AH + row * LDP + fcol) = make_uint2(h0, h1);
            *(uint2*)(AL + row * LDP + fcol) = make_uint2(l0, l1);
            split2(wv.x, wv.y, h0, l0); split2(wv.z, wv.w, h1, l1);
            *(uint2*)(WH + row * LDP + fcol) = make_uint2(h0, h1);
            *(uint2*)(WL + row * LDP + fcol) = make_uint2(l0, l1);
        }
    }
    __syncthreads();

    for (int it = 0; it < 20; it++) {
        const int cur = it & 1;
        const __nv_bfloat16* AH = sm + cur * D_BUF;
        const __nv_bfloat16* AL = AH + D_T;
        const __nv_bfloat16* WH = AH + 2 * D_T;
        const __nv_bfloat16* WL = AH + 3 * D_T;

        float4 xv[4], wv[4];
        if (it + 1 < 20) {
            const int kc = (it + 1) * 64;
#pragma unroll
            for (int p = 0; p < 4; p++) {
                const int row = p * 16 + frow;
                xv[p] = *(const float4*)(xb + (size_t)row * DIN + kc + fcol);
                wv[p] = *(const float4*)(wd + (size_t)row * DIN + kc + fcol);
            }
        }

#pragma unroll
        for (int kk = 0; kk < 4; kk++) {
            const int kb = kk * 16 + tg * 2;
            uint32_t aH[4], aL[4];
            aH[0] = *(const uint32_t*)(AH + (m0 + g)     * LDP + kb);
            aH[1] = *(const uint32_t*)(AH + (m0 + g + 8) * LDP + kb);
            aH[2] = *(const uint32_t*)(AH + (m0 + g)     * LDP + kb + 8);
            aH[3] = *(const uint32_t*)(AH + (m0 + g + 8) * LDP + kb + 8);
            aL[0] = *(const uint32_t*)(AL + (m0 + g)     * LDP + kb);
            aL[1] = *(const uint32_t*)(AL + (m0 + g + 8) * LDP + kb);
            aL[2] = *(const uint32_t*)(AL + (m0 + g)     * LDP + kb + 8);
            aL[3] = *(const uint32_t*)(AL + (m0 + g + 8) * LDP + kb + 8);
#pragma unroll
            for (int u = 0; u < 4; u++) {
                const int nr = n0 + u * 8 + g;
                uint32_t bH[2], bL[2];
                bH[0] = *(const uint32_t*)(WH + nr * LDP + kb);
                bH[1] = *(const uint32_t*)(WH + nr * LDP + kb + 8);
                bL[0] = *(const uint32_t*)(WL + nr * LDP + kb);
                bL[1] = *(const uint32_t*)(WL + nr * LDP + kb + 8);
                mma16816(acc[u], aH, bH);
                mma16816(acc[u], aH, bL);
                mma16816(acc[u], aL, bH);
            }
        }

        if (it + 1 < 20) {
            __nv_bfloat16* nAH = sm + (cur ^ 1) * D_BUF;
            __nv_bfloat16* nAL = nAH + D_T;
            __nv_bfloat16* nWH = nAH + 2 * D_T;
            __nv_bfloat16* nWL = nAH + 3 * D_T;
#pragma unroll
            for (int p = 0; p < 4; p++) {
                const int row = p * 16 + frow;
                uint32_t h0, l0, h1, l1;
                split2(xv[p].x, xv[p].y, h0, l0); split2(xv[p].z, xv[p].w, h1, l1);
                *(uint2*)(nAH + row * LDP + fcol) = make_uint2(h0, h1);
                *(uint2*)(nAL + row * LDP + fcol) = make_uint2(l0, l1);
                split2(wv[p].x, wv[p].y, h0, l0); split2(wv[p].z, wv[p].w, h1, l1);
                *(uint2*)(nWH + row * LDP + fcol) = make_uint2(h0, h1);
                *(uint2*)(nWL + row * LDP + fcol) = make_uint2(l0, l1);
            }
            __syncthreads();
        }
    }

    // epilogue: split h to bf16 hi/lo, write as b32 pairs
    const size_t srow = (size_t)b * SQ + s0;
#pragma unroll
    for (int u = 0; u < 4; u++) {
        const int c = n0 + u * 8 + tg * 2;
        uint32_t hi, lo;
        const size_t i0 = (srow + m0 + g) * RNK + c;
        split2(acc[u][0], acc[u][1], hi, lo);
        *(uint32_t*)(g_hh + i0) = hi; *(uint32_t*)(g_hl + i0) = lo;
        const size_t i1 = (srow + m0 + g + 8) * RNK + c;
        split2(acc[u][2], acc[u][3], hi, lo);
        *(uint32_t*)(g_hh + i1) = hi; *(uint32_t*)(g_hl + i1) = lo;
    }
}

// ============================================================================
// k_up: out[b,s,o] = sum_r h[b,s,r] * w_up[b,o,r]
// tile 128(s) x 128(o), K=64 loaded once.
// 256 thr = 8 warps (2m x 4n), warp tile 64x32 -> 4 m-tiles x 4 n-tiles.
// grid (8 s-tiles, 10 o-tiles, 8 b) = 640 CTAs.
// ============================================================================
static constexpr int U_T = 128 * LDP;
static constexpr int SMEM_UP = 4 * U_T * 2;    // 73728 B

__global__ __launch_bounds__(256)
void k_up(const float* __restrict__ embed, float* __restrict__ out) {
    extern __shared__ __nv_bfloat16 sm[];
    __nv_bfloat16* HH = sm;
    __nv_bfloat16* HL = sm + U_T;
    __nv_bfloat16* WH = sm + 2 * U_T;
    __nv_bfloat16* WL = sm + 3 * U_T;

    const int tid = threadIdx.x, lane = tid & 31, wid = tid >> 5;
    const int b = blockIdx.z, s0 = blockIdx.x * 128, o0 = blockIdx.y * 128;
    const float* __restrict__ wp = embed + (size_t)b * EMBSZ + DOWNSZ
                                   + (size_t)o0 * RNK;          // [o][r]
    const __nv_bfloat16* __restrict__ ghh = g_hh;
    const __nv_bfloat16* __restrict__ ghl = g_hl;
    const size_t hbase = ((size_t)b * SQ + s0) * RNK;

    {
        const int r16 = tid >> 4;           // 0..15
        const int uc  = tid & 15;           // uint2 col -> k = uc*4
        const int fcol = (tid & 15) * 4;
#pragma unroll
        for (int p = 0; p < 8; p++) {
            const int row = p * 16 + r16;
            uint2 vh = *(const uint2*)(ghh + hbase + (size_t)row * RNK + uc * 4);
            uint2 vl = *(const uint2*)(ghl + hbase + (size_t)row * RNK + uc * 4);
            *(uint2*)(HH + row * LDP + uc * 4) = vh;
            *(uint2*)(HL + row * LDP + uc * 4) = vl;
            float4 v = *(const float4*)(wp + (size_t)row * RNK + fcol);
            uint32_t h0, l0, h1, l1;
            split2(v.x, v.y, h0, l0); split2(v.z, v.w, h1, l1);
            *(uint2*)(WH + row * LDP + fcol) = make_uint2(h0, h1);
            *(uint2*)(WL + row * LDP + fcol) = make_uint2(l0, l1);
        }
    }
    __syncthreads();

    const int wm = wid >> 2, wn = wid & 3;
    const int m0 = wm * 64, n0 = wn * 32;
    const int g = lane >> 2, tg = lane & 3;

    float acc[4][4][4];
#pragma unroll
    for (int t = 0; t < 4; t++)
#pragma unroll
        for (int u = 0; u < 4; u++)
#pragma unroll
            for (int j = 0; j < 4; j++) acc[t][u][j] = 0.f;

#pragma unroll
    for (int kk = 0; kk < 4; kk++) {
        const int kb = kk * 16 + tg * 2;
        uint32_t aH[4][4], aL[4][4];
#pragma unroll
        for (int t = 0; t < 4; t++) {
            const int r0 = m0 + t * 16 + g;
            aH[t][0] = *(const uint32_t*)(HH + r0       * LDP + kb);
            aH[t][1] = *(const uint32_t*)(HH + (r0 + 8) * LDP + kb);
            aH[t][2] = *(const uint32_t*)(HH + r0       * LDP + kb + 8);
            aH[t][3] = *(const uint32_t*)(HH + (r0 + 8) * LDP + kb + 8);
            aL[t][0] = *(const uint32_t*)(HL + r0       * LDP + kb);
            aL[t][1] = *(const uint32_t*)(HL + (r0 + 8) * LDP + kb);
            aL[t][2] = *(const uint32_t*)(HL + r0       * LDP + kb + 8);
            aL[t][3] = *(const uint32_t*)(HL + (r0 + 8) * LDP + kb + 8);
        }
#pragma unroll
        for (int u = 0; u < 4; u++) {
            const int nr = n0 + u * 8 + g;
            uint32_t bH[2], bL[2];
            bH[0] = *(const uint32_t*)(WH + nr * LDP + kb);
            bH[1] = *(const uint32_t*)(WH + nr * LDP + kb + 8);
            bL[0] = *(const uint32_t*)(WL + nr * LDP + kb);
            bL[1] = *(const uint32_t*)(WL + nr * LDP + kb + 8);
#pragma unroll
            for (int t = 0; t < 4; t++) {
                mma16816(acc[t][u], aH[t], bH);
                mma16816(acc[t][u], aH[t], bL);
                mma16816(acc[t][u], aL[t], bH);
            }
        }
    }

    // epilogue: fp32 out, float2 stores (sector-complete per warp row)
#pragma unroll
    for (int t = 0; t < 4; t++) {
        const size_t r0 = (size_t)b * SQ + s0 + m0 + t * 16 + g;
#pragma unroll
        for (int u = 0; u < 4; u++) {
            const int c = o0 + n0 + u * 8 + tg * 2;
            *(float2*)(out + r0 * DOUT + c)       = make_float2(acc[t][u][0], acc[t][u][1]);
            *(float2*)(out + (r0 + 8) * DOUT + c) = make_float2(acc[t][u][2], acc[t][u][3]);
        }
    }
}

extern "C" void kernel_launch(void* const* d_in, const int* in_sizes, int n_in,
                              void* d_out, int out_size) {
    const float* x     = (const float*)d_in[0];   // [8,1024,1280]
    const float* embed = (const float*)d_in[1];   // [8,163840]
    float*       out   = (float*)d_out;           // [8,1024,1280]
    (void)in_sizes; (void)n_in; (void)out_size;

    cudaFuncSetAttribute(k_down, cudaFuncAttributeMaxDynamicSharedMemorySize, SMEM_DOWN);
    cudaFuncSetAttribute(k_up,   cudaFuncAttributeMaxDynamicSharedMemorySize, SMEM_UP);

    k_down<<<dim3(16, 8), 256, SMEM_DOWN>>>(x, embed);
    k_up<<<dim3(8, 10, 8), 256, SMEM_UP>>>(embed, out);
}

// round 6
// speedup vs baseline: 2.0343x; 1.2815x over previous
#include <cuda_runtime.h>
#include <cuda_bf16.h>
#include <cstdint>

#define NB 8
#define SQ 1024
#define DIN 1280
#define RNK 64
#define DOUT 1280
#define DOWNSZ (RNK*DIN)
#define UPSZ (DOUT*RNK)
#define EMBSZ (DOWNSZ+UPSZ)

#define LDP  72           // padded row stride (bf16 elems); 144 B -> conflict-free ldmatrix
#define LDPB (LDP*2)

// pre-split embed (hi/lo bf16), split-K h partials
__device__ __nv_bfloat16 g_eh[NB*EMBSZ];
__device__ __nv_bfloat16 g_el[NB*EMBSZ];
__device__ float g_hp[2][NB*SQ*RNK];

__device__ __forceinline__ uint32_t smem_u32(const void* p) {
    uint32_t a;
    asm("{ .reg .u64 t; cvta.to.shared.u64 t, %1; cvt.u32.u64 %0, t; }" : "=r"(a) : "l"(p));
    return a;
}

// truncation split: hi = top16(a) (exact bf16), lo = rn_bf16(a - hi)
__device__ __forceinline__ void split2f(float a, float b, uint32_t& hi, uint32_t& lo) {
    uint32_t ua = __float_as_uint(a), ub = __float_as_uint(b);
    uint32_t h;
    asm("prmt.b32 %0, %1, %2, 0x7632;" : "=r"(h) : "r"(ua), "r"(ub));
    float ra = a - __uint_as_float(ua & 0xFFFF0000u);
    float rb = b - __uint_as_float(ub & 0xFFFF0000u);
    uint32_t l;
    asm("cvt.rn.bf16x2.f32 %0, %1, %2;" : "=r"(l) : "f"(rb), "f"(ra)); // hi-half=rb
    hi = h; lo = l;
}

__device__ __forceinline__ void mma16816(float* d, const uint32_t* a, const uint32_t* b) {
    asm volatile("mma.sync.aligned.m16n8k16.row.col.f32.bf16.bf16.f32 "
        "{%0,%1,%2,%3}, {%4,%5,%6,%7}, {%8,%9}, {%0,%1,%2,%3};"
        : "+f"(d[0]), "+f"(d[1]), "+f"(d[2]), "+f"(d[3])
        : "r"(a[0]), "r"(a[1]), "r"(a[2]), "r"(a[3]), "r"(b[0]), "r"(b[1]));
}
#define LDSM4(R, addr) \
    asm volatile("ldmatrix.sync.aligned.m8n8.x4.shared.b16 {%0,%1,%2,%3}, [%4];" \
        : "=r"((R)[0]), "=r"((R)[1]), "=r"((R)[2]), "=r"((R)[3]) : "r"(addr))

// ============================================================================
// k_prep: split embed -> g_eh/g_el.  float4 per thread.
// ============================================================================
__global__ __launch_bounds__(256)
void k_prep(const float* __restrict__ embed) {
    const size_t i = ((size_t)blockIdx.x * 256 + threadIdx.x) * 4;
    if (i >= (size_t)NB * EMBSZ) return;
    float4 v = *(const float4*)(embed + i);
    uint32_t h0, l0, h1, l1;
    split2f(v.x, v.y, h0, l0); split2f(v.z, v.w, h1, l1);
    *(uint2*)(g_eh + i) = make_uint2(h0, h1);
    *(uint2*)(g_el + i) = make_uint2(l0, l1);
}

// ============================================================================
// k_down: partial h = x @ w_down^T over K-chunk kc (640 each)
// tile 64(s) x 64(r); 10 chunks of 64; double-buffered; 8 warps (4m x 2n).
// grid (16 s, 2 kc, 8 b) = 256 CTAs, 256 thr.
// ============================================================================
static constexpr int D_T   = 64 * LDP;
static constexpr int D_BUF = 4 * D_T;             // AH AL WH WL
static constexpr int SMEM_DOWN = 2 * D_BUF * 2;   // 73728 B

__global__ __launch_bounds__(256)
void k_down(const float* __restrict__ x) {
    extern __shared__ __nv_bfloat16 sm[];
    const uint32_t smb = smem_u32(sm);
    const int tid = threadIdx.x, lane = tid & 31, wid = tid >> 5;
    const int b = blockIdx.z, kcb = blockIdx.y, s0 = blockIdx.x * 64;
    const int kbase = kcb * 640;
    const float* __restrict__ xb = x + ((size_t)b * SQ + s0) * DIN + kbase;
    const __nv_bfloat16* __restrict__ weh = g_eh + (size_t)b * EMBSZ + kbase; // [r][DIN]
    const __nv_bfloat16* __restrict__ wel = g_el + (size_t)b * EMBSZ + kbase;

    const int frow = tid >> 4, fcol = (tid & 15) * 4;     // x fill
    const int wrow = tid >> 2, wc = (tid & 3) * 16;       // w fill
    const int wm = wid >> 1, wn = wid & 1;
    const int m0 = wm * 16, n0 = wn * 32;
    const int r8 = lane & 7, gq = lane >> 3;

    // lane ldmatrix byte offsets within a tile
    const uint32_t offA  = (uint32_t)(m0 + r8 + (gq & 1) * 8) * LDPB + (gq >> 1) * 16;
    const uint32_t offB0 = (uint32_t)(n0 + 0 * 8 + r8 + (gq >> 1) * 8) * LDPB + (gq & 1) * 16;
    const uint32_t offB2 = (uint32_t)(n0 + 2 * 8 + r8 + (gq >> 1) * 8) * LDPB + (gq & 1) * 16;

    float acc[4][4];
#pragma unroll
    for (int u = 0; u < 4; u++)
#pragma unroll
        for (int j = 0; j < 4; j++) acc[u][j] = 0.f;

    // fill buffer 0
    {
        __nv_bfloat16* AH = sm;           __nv_bfloat16* AL = sm + D_T;
        __nv_bfloat16* WH = sm + 2 * D_T; __nv_bfloat16* WL = sm + 3 * D_T;
#pragma unroll
        for (int p = 0; p < 4; p++) {
            const int row = p * 16 + frow;
            float4 v = *(const float4*)(xb + (size_t)row * DIN + fcol);
            uint32_t h0, l0, h1, l1;
            split2f(v.x, v.y, h0, l0); split2f(v.z, v.w, h1, l1);
            *(uint2*)(AH + row * LDP + fcol) = make_uint2(h0, h1);
            *(uint2*)(AL + row * LDP + fcol) = make_uint2(l0, l1);
        }
#pragma unroll
        for (int q = 0; q < 2; q++) {
            *(uint4*)(WH + wrow * LDP + wc + q * 8) =
                *(const uint4*)(weh + (size_t)wrow * DIN + wc + q * 8);
            *(uint4*)(WL + wrow * LDP + wc + q * 8) =
                *(const uint4*)(wel + (size_t)wrow * DIN + wc + q * 8);
        }
    }
    __syncthreads();

    for (int it = 0; it < 10; it++) {
        const uint32_t base = smb + (it & 1) * (D_BUF * 2);

        float4 xv[4]; uint4 wh[2], wl[2];
        if (it + 1 < 10) {
            const int kc = (it + 1) * 64;
#pragma unroll
            for (int p = 0; p < 4; p++)
                xv[p] = *(const float4*)(xb + (size_t)(p * 16 + frow) * DIN + kc + fcol);
#pragma unroll
            for (int q = 0; q < 2; q++) {
                wh[q] = *(const uint4*)(weh + (size_t)wrow * DIN + kc + wc + q * 8);
                wl[q] = *(const uint4*)(wel + (size_t)wrow * DIN + kc + wc + q * 8);
            }
        }

        const uint32_t AH = base, AL = base + D_T * 2, WH = base + 4 * D_T, WL = base + 6 * D_T;
#pragma unroll
        for (int kk = 0; kk < 4; kk++) {
            const uint32_t ko = kk * 32;
            uint32_t aH[4], aL[4], bH[4], bL[4], bH2[4], bL2[4];
            LDSM4(aH, AH + offA + ko);
            LDSM4(aL, AL + offA + ko);
            LDSM4(bH, WH + offB0 + ko);
            LDSM4(bL, WL + offB0 + ko);
            LDSM4(bH2, WH + offB2 + ko);
            LDSM4(bL2, WL + offB2 + ko);
            mma16816(acc[0], aH, bH);      mma16816(acc[0], aH, bL);      mma16816(acc[0], aL, bH);
            mma16816(acc[1], aH, bH + 2);  mma16816(acc[1], aH, bL + 2);  mma16816(acc[1], aL, bH + 2);
            mma16816(acc[2], aH, bH2);     mma16816(acc[2], aH, bL2);     mma16816(acc[2], aL, bH2);
            mma16816(acc[3], aH, bH2 + 2); mma16816(acc[3], aH, bL2 + 2); mma16816(acc[3], aL, bH2 + 2);
        }

        if (it + 1 < 10) {
            __syncthreads();
            __nv_bfloat16* nb = sm + ((it + 1) & 1) * D_BUF;
            __nv_bfloat16* AHn = nb;           __nv_bfloat16* ALn = nb + D_T;
            __nv_bfloat16* WHn = nb + 2 * D_T; __nv_bfloat16* WLn = nb + 3 * D_T;
#pragma unroll
            for (int p = 0; p < 4; p++) {
                const int row = p * 16 + frow;
                uint32_t h0, l0, h1, l1;
                split2f(xv[p].x, xv[p].y, h0, l0); split2f(xv[p].z, xv[p].w, h1, l1);
                *(uint2*)(AHn + row * LDP + fcol) = make_uint2(h0, h1);
                *(uint2*)(ALn + row * LDP + fcol) = make_uint2(l0, l1);
            }
#pragma unroll
            for (int q = 0; q < 2; q++) {
                *(uint4*)(WHn + wrow * LDP + wc + q * 8) = wh[q];
                *(uint4*)(WLn + wrow * LDP + wc + q * 8) = wl[q];
            }
            __syncthreads();
        }
    }

    // fp32 partials
    float* hp = g_hp[kcb] + ((size_t)b * SQ + s0) * RNK;
    const int g = lane >> 2, tg = lane & 3;
#pragma unroll
    for (int u = 0; u < 4; u++) {
        const int c = n0 + u * 8 + tg * 2;
        *(float2*)(hp + (size_t)(m0 + g) * RNK + c)     = make_float2(acc[u][0], acc[u][1]);
        *(float2*)(hp + (size_t)(m0 + g + 8) * RNK + c) = make_float2(acc[u][2], acc[u][3]);
    }
}

// ============================================================================
// k_up: out = h @ w_up^T ;  h = hp0+hp1 summed+split in fill.
// tile 64(s) x 128(o), K=64 once; 8 warps (2m x 4n), warp tile 32x32.
// grid (16 s, 10 o, 8 b) = 1280 CTAs, 256 thr.
// ============================================================================
static constexpr int U_HT = 64 * LDP;
static constexpr int U_WT = 128 * LDP;
static constexpr int SMEM_UP = (2 * U_HT + 2 * U_WT) * 2;  // 55296 B

__global__ __launch_bounds__(256)
void k_up(float* __restrict__ out) {
    extern __shared__ __nv_bfloat16 sm[];
    __nv_bfloat16* HH = sm;
    __nv_bfloat16* HL = sm + U_HT;
    __nv_bfloat16* WH = sm + 2 * U_HT;
    __nv_bfloat16* WL = sm + 2 * U_HT + U_WT;
    const uint32_t smb = smem_u32(sm);

    const int tid = threadIdx.x, lane = tid & 31, wid = tid >> 5;
    const int b = blockIdx.z, s0 = blockIdx.x * 64, o0 = blockIdx.y * 128;
    const float* __restrict__ h0p = g_hp[0] + ((size_t)b * SQ + s0) * RNK;
    const float* __restrict__ h1p = g_hp[1] + ((size_t)b * SQ + s0) * RNK;
    const __nv_bfloat16* __restrict__ weh = g_eh + (size_t)b * EMBSZ + DOWNSZ + (size_t)o0 * RNK;
    const __nv_bfloat16* __restrict__ wel = g_el + (size_t)b * EMBSZ + DOWNSZ + (size_t)o0 * RNK;

    // h fill: 64 rows x 64 cols fp32, sum partials + split
    {
        const int frow = tid >> 4, fcol = (tid & 15) * 4;
#pragma unroll
        for (int p = 0; p < 4; p++) {
            const int row = p * 16 + frow;
            float4 a = *(const float4*)(h0p + (size_t)row * RNK + fcol);
            float4 c = *(const float4*)(h1p + (size_t)row * RNK + fcol);
            uint32_t h0, l0, h1, l1;
            split2f(a.x + c.x, a.y + c.y, h0, l0);
            split2f(a.z + c.z, a.w + c.w, h1, l1);
            *(uint2*)(HH + row * LDP + fcol) = make_uint2(h0, h1);
            *(uint2*)(HL + row * LDP + fcol) = make_uint2(l0, l1);
        }
    }
    // w_up fill: 128 rows x 64 cols bf16 copy
    {
        const int r2 = tid >> 2, c16 = (tid & 3) * 16;
#pragma unroll
        for (int p = 0; p < 2; p++) {
            const int row = p * 64 + r2;
#pragma unroll
            for (int q = 0; q < 2; q++) {
                *(uint4*)(WH + row * LDP + c16 + q * 8) =
                    *(const uint4*)(weh + (size_t)row * RNK + c16 + q * 8);
                *(uint4*)(WL + row * LDP + c16 + q * 8) =
                    *(const uint4*)(wel + (size_t)row * RNK + c16 + q * 8);
            }
        }
    }
    __syncthreads();

    const int wm = wid >> 2, wn = wid & 3;
    const int m0 = wm * 32, n0 = wn * 32;
    const int r8 = lane & 7, gq = lane >> 3;

    const uint32_t HHa = smb, HLa = smb + U_HT * 2;
    const uint32_t WHa = smb + 4 * U_HT, WLa = smb + 4 * U_HT + 2 * U_WT;
    const uint32_t offA0 = (uint32_t)(m0 + r8 + (gq & 1) * 8) * LDPB + (gq >> 1) * 16;
    const uint32_t offA1 = offA0 + 16 * LDPB;
    const uint32_t offB0 = (uint32_t)(n0 + r8 + (gq >> 1) * 8) * LDPB + (gq & 1) * 16;
    const uint32_t offB2 = offB0 + 16 * LDPB;

    float acc[2][4][4];
#pragma unroll
    for (int t = 0; t < 2; t++)
#pragma unroll
        for (int u = 0; u < 4; u++)
#pragma unroll
            for (int j = 0; j < 4; j++) acc[t][u][j] = 0.f;

#pragma unroll
    for (int kk = 0; kk < 4; kk++) {
        const uint32_t ko = kk * 32;
        uint32_t aH0[4], aL0[4], aH1[4], aL1[4];
        uint32_t bH[4], bL[4], bH2[4], bL2[4];
        LDSM4(aH0, HHa + offA0 + ko);
        LDSM4(aL0, HLa + offA0 + ko);
        LDSM4(aH1, HHa + offA1 + ko);
        LDSM4(aL1, HLa + offA1 + ko);
        LDSM4(bH, WHa + offB0 + ko);
        LDSM4(bL, WLa + offB0 + ko);
        LDSM4(bH2, WHa + offB2 + ko);
        LDSM4(bL2, WLa + offB2 + ko);
#pragma unroll
        for (int t = 0; t < 2; t++) {
            const uint32_t* aH = t ? aH1 : aH0;
            const uint32_t* aL = t ? aL1 : aL0;
            mma16816(acc[t][0], aH, bH);      mma16816(acc[t][0], aH, bL);      mma16816(acc[t][0], aL, bH);
            mma16816(acc[t][1], aH, bH + 2);  mma16816(acc[t][1], aH, bL + 2);  mma16816(acc[t][1], aL, bH + 2);
            mma16816(acc[t][2], aH, bH2);     mma16816(acc[t][2], aH, bL2);     mma16816(acc[t][2], aL, bH2);
            mma16816(acc[t][3], aH, bH2 + 2); mma16816(acc[t][3], aH, bL2 + 2); mma16816(acc[t][3], aL, bH2 + 2);
        }
    }

    const int g = lane >> 2, tg = lane & 3;
#pragma unroll
    for (int t = 0; t < 2; t++) {
        const size_t r0 = (size_t)b * SQ + s0 + m0 + t * 16 + g;
#pragma unroll
        for (int u = 0; u < 4; u++) {
            const int c = o0 + n0 + u * 8 + tg * 2;
            *(float2*)(out + r0 * DOUT + c)       = make_float2(acc[t][u][0], acc[t][u][1]);
            *(float2*)(out + (r0 + 8) * DOUT + c) = make_float2(acc[t][u][2], acc[t][u][3]);
        }
    }
}

extern "C" void kernel_launch(void* const* d_in, const int* in_sizes, int n_in,
                              void* d_out, int out_size) {
    const float* x     = (const float*)d_in[0];   // [8,1024,1280]
    const float* embed = (const float*)d_in[1];   // [8,163840]
    float*       out   = (float*)d_out;           // [8,1024,1280]
    (void)in_sizes; (void)n_in; (void)out_size;

    cudaFuncSetAttribute(k_down, cudaFuncAttributeMaxDynamicSharedMemorySize, SMEM_DOWN);
    cudaFuncSetAttribute(k_up,   cudaFuncAttributeMaxDynamicSharedMemorySize, SMEM_UP);

    const int prep_blocks = (NB * EMBSZ / 4 + 255) / 256;
    k_prep<<<prep_blocks, 256>>>(embed);
    k_down<<<dim3(16, 2, 8), 256, SMEM_DOWN>>>(x);
    k_up<<<dim3(16, 10, 8), 256, SMEM_UP>>>(out);
}

// round 8
// speedup vs baseline: 2.2859x; 1.1237x over previous
#include <cuda_runtime.h>
#include <cuda_bf16.h>
#include <cstdint>

#define NB 8
#define SQ 1024
#define DIN 1280
#define RNK 64
#define DOUT 1280
#define DOWNSZ (RNK*DIN)
#define UPSZ (DOUT*RNK)
#define EMBSZ (DOWNSZ+UPSZ)

#define LDP  72           // padded row stride (bf16 elems); 144 B
#define LDPB (LDP*2)

// pre-split embed (hi/lo bf16), split-K h partials
__device__ __nv_bfloat16 g_eh[NB*EMBSZ];
__device__ __nv_bfloat16 g_el[NB*EMBSZ];
__device__ float g_hp[2][NB*SQ*RNK];

__device__ __forceinline__ uint32_t smem_u32(const void* p) {
    uint32_t a;
    asm("{ .reg .u64 t; cvta.to.shared.u64 t, %1; cvt.u32.u64 %0, t; }" : "=r"(a) : "l"(p));
    return a;
}
// truncation split: hi = top16(a), lo = rn_bf16(a - hi)
__device__ __forceinline__ void split2f(float a, float b, uint32_t& hi, uint32_t& lo) {
    uint32_t ua = __float_as_uint(a), ub = __float_as_uint(b);
    uint32_t h;
    asm("prmt.b32 %0, %1, %2, 0x7632;" : "=r"(h) : "r"(ua), "r"(ub));
    float ra = a - __uint_as_float(ua & 0xFFFF0000u);
    float rb = b - __uint_as_float(ub & 0xFFFF0000u);
    uint32_t l;
    asm("cvt.rn.bf16x2.f32 %0, %1, %2;" : "=r"(l) : "f"(rb), "f"(ra));
    hi = h; lo = l;
}
__device__ __forceinline__ void mma16816(float* d, const uint32_t* a, const uint32_t* b) {
    asm volatile("mma.sync.aligned.m16n8k16.row.col.f32.bf16.bf16.f32 "
        "{%0,%1,%2,%3}, {%4,%5,%6,%7}, {%8,%9}, {%0,%1,%2,%3};"
        : "+f"(d[0]), "+f"(d[1]), "+f"(d[2]), "+f"(d[3])
        : "r"(a[0]), "r"(a[1]), "r"(a[2]), "r"(a[3]), "r"(b[0]), "r"(b[1]));
}
#define LDSM4(R, addr) \
    asm volatile("ldmatrix.sync.aligned.m8n8.x4.shared.b16 {%0,%1,%2,%3}, [%4];" \
        : "=r"((R)[0]), "=r"((R)[1]), "=r"((R)[2]), "=r"((R)[3]) : "r"(addr))
__device__ __forceinline__ void cpa16(uint32_t dst, const void* src) {
    asm volatile("cp.async.cg.shared.global [%0], [%1], 16;" :: "r"(dst), "l"(src));
}
#define CP_COMMIT asm volatile("cp.async.commit_group;" ::: "memory")
#define CP_WAIT0  asm volatile("cp.async.wait_group 0;" ::: "memory")

// ============================================================================
// k_prep: split embed -> g_eh/g_el. 16 elems/thread, 320 blocks (exact).
// ============================================================================
__global__ __launch_bounds__(256)
void k_prep(const float* __restrict__ embed) {
    const size_t i = ((size_t)blockIdx.x * 256 + threadIdx.x) * 16;
#pragma unroll
    for (int q = 0; q < 2; q++) {
        float4 v0 = *(const float4*)(embed + i + q * 8);
        float4 v1 = *(const float4*)(embed + i + q * 8 + 4);
        uint32_t h0, l0, h1, l1, h2, l2, h3, l3;
        split2f(v0.x, v0.y, h0, l0); split2f(v0.z, v0.w, h1, l1);
        split2f(v1.x, v1.y, h2, l2); split2f(v1.z, v1.w, h3, l3);
        *(uint4*)(g_eh + i + q * 8) = make_uint4(h0, h1, h2, h3);
        *(uint4*)(g_el + i + q * 8) = make_uint4(l0, l1, l2, l3);
    }
}

// ============================================================================
// k_down: partial h = x @ w_down^T over K-chunk (640 each)
// tile 64(s) x 64(r); 10 chunks of 64; double-buffered; cp.async W; 1 sync/iter.
// grid (16 s, 2 kc, 8 b) = 256 CTAs, 256 thr.
// ============================================================================
static constexpr int D_T   = 64 * LDP;            // elems per tile (4608)
static constexpr int D_BUF = 4 * D_T;             // AH AL WH WL
static constexpr int SMEM_DOWN = 2 * D_BUF * 2;   // 73728 B

__global__ __launch_bounds__(256)
void k_down(const float* __restrict__ x) {
    extern __shared__ __nv_bfloat16 sm[];
    const uint32_t smb = smem_u32(sm);
    const int tid = threadIdx.x, lane = tid & 31, wid = tid >> 5;
    const int b = blockIdx.z, kcb = blockIdx.y, s0 = blockIdx.x * 64;
    const int kbase = kcb * 640;
    const float* __restrict__ xb = x + ((size_t)b * SQ + s0) * DIN + kbase;
    const __nv_bfloat16* __restrict__ weh = g_eh + (size_t)b * EMBSZ + kbase; // [r][DIN]
    const __nv_bfloat16* __restrict__ wel = g_el + (size_t)b * EMBSZ + kbase;

    const int frow = tid >> 4, fcol = (tid & 15) * 4;     // x fill
    const int wrow = tid >> 3, wc8 = (tid & 7) * 8;       // W cp.async: 2 passes of 32 rows
    const int wm = wid >> 1, wn = wid & 1;
    const int m0 = wm * 16, n0 = wn * 32;
    const int r8 = lane & 7, gq = lane >> 3;

    const uint32_t offA  = (uint32_t)(m0 + r8 + (gq & 1) * 8) * LDPB + (gq >> 1) * 16;
    const uint32_t offB0 = (uint32_t)(n0 + 0 * 8 + r8 + (gq >> 1) * 8) * LDPB + (gq & 1) * 16;
    const uint32_t offB2 = (uint32_t)(n0 + 2 * 8 + r8 + (gq >> 1) * 8) * LDPB + (gq & 1) * 16;

    float acc[4][4];
#pragma unroll
    for (int u = 0; u < 4; u++)
#pragma unroll
        for (int j = 0; j < 4; j++) acc[u][j] = 0.f;

    // ---- prolog: buffer 0 ----
    {
        const uint32_t WHb = smb + 4 * D_T, WLb = smb + 6 * D_T;   // byte offsets
#pragma unroll
        for (int p = 0; p < 2; p++) {
            const int row = wrow + p * 32;
            cpa16(WHb + (uint32_t)(row * LDP + wc8) * 2, weh + (size_t)row * DIN + wc8);
            cpa16(WLb + (uint32_t)(row * LDP + wc8) * 2, wel + (size_t)row * DIN + wc8);
        }
        CP_COMMIT;
        __nv_bfloat16* AH = sm; __nv_bfloat16* AL = sm + D_T;
#pragma unroll
        for (int p = 0; p < 4; p++) {
            const int row = p * 16 + frow;
            float4 v = *(const float4*)(xb + (size_t)row * DIN + fcol);
            uint32_t h0, l0, h1, l1;
            split2f(v.x, v.y, h0, l0); split2f(v.z, v.w, h1, l1);
            *(uint2*)(AH + row * LDP + fcol) = make_uint2(h0, h1);
            *(uint2*)(AL + row * LDP + fcol) = make_uint2(l0, l1);
        }
        CP_WAIT0;
    }
    __syncthreads();

    for (int it = 0; it < 10; it++) {
        const uint32_t base = smb + (it & 1) * (D_BUF * 2);
        const uint32_t nbase = smb + ((it + 1) & 1) * (D_BUF * 2);

        float4 xv[4];
        if (it + 1 < 10) {
            const int kc = (it + 1) * 64;
            // async W(next) — target buffer was last read 2 iters ago (fenced)
#pragma unroll
            for (int p = 0; p < 2; p++) {
                const int row = wrow + p * 32;
                cpa16(nbase + 4 * D_T + (uint32_t)(row * LDP + wc8) * 2,
                      weh + (size_t)row * DIN + kc + wc8);
                cpa16(nbase + 6 * D_T + (uint32_t)(row * LDP + wc8) * 2,
                      wel + (size_t)row * DIN + kc + wc8);
            }
            CP_COMMIT;
#pragma unroll
            for (int p = 0; p < 4; p++)
                xv[p] = *(const float4*)(xb + (size_t)(p * 16 + frow) * DIN + kc + fcol);
        }

        const uint32_t AH = base, AL = base + 2 * D_T, WH = base + 4 * D_T, WL = base + 6 * D_T;
#pragma unroll
        for (int kk = 0; kk < 4; kk++) {
            const uint32_t ko = kk * 32;
            uint32_t aH[4], aL[4], bH[4], bL[4], bH2[4], bL2[4];
            LDSM4(aH, AH + offA + ko);
            LDSM4(aL, AL + offA + ko);
            LDSM4(bH, WH + offB0 + ko);
            LDSM4(bL, WL + offB0 + ko);
            LDSM4(bH2, WH + offB2 + ko);
            LDSM4(bL2, WL + offB2 + ko);
            mma16816(acc[0], aH, bH);      mma16816(acc[0], aH, bL);      mma16816(acc[0], aL, bH);
            mma16816(acc[1], aH, bH + 2);  mma16816(acc[1], aH, bL + 2);  mma16816(acc[1], aL, bH + 2);
            mma16816(acc[2], aH, bH2);     mma16816(acc[2], aH, bL2);     mma16816(acc[2], aL, bH2);
            mma16816(acc[3], aH, bH2 + 2); mma16816(acc[3], aH, bL2 + 2); mma16816(acc[3], aL, bH2 + 2);
        }

        if (it + 1 < 10) {
            __nv_bfloat16* nb = sm + ((it + 1) & 1) * D_BUF;
            __nv_bfloat16* AHn = nb; __nv_bfloat16* ALn = nb + D_T;
#pragma unroll
            for (int p = 0; p < 4; p++) {
                const int row = p * 16 + frow;
                uint32_t h0, l0, h1, l1;
                split2f(xv[p].x, xv[p].y, h0, l0); split2f(xv[p].z, xv[p].w, h1, l1);
                *(uint2*)(AHn + row * LDP + fcol) = make_uint2(h0, h1);
                *(uint2*)(ALn + row * LDP + fcol) = make_uint2(l0, l1);
            }
            CP_WAIT0;
            __syncthreads();
        }
    }

    float* hp = g_hp[kcb] + ((size_t)b * SQ + s0) * RNK;
    const int g = lane >> 2, tg = lane & 3;
#pragma unroll
    for (int u = 0; u < 4; u++) {
        const int c = n0 + u * 8 + tg * 2;
        *(float2*)(hp + (size_t)(m0 + g) * RNK + c)     = make_float2(acc[u][0], acc[u][1]);
        *(float2*)(hp + (size_t)(m0 + g + 8) * RNK + c) = make_float2(acc[u][2], acc[u][3]);
    }
}

// ============================================================================
// k_up: out = h @ w_up^T ;  h = hp0+hp1 summed+split in fill; W via cp.async.
// tile 64(s) x 128(o), K=64 once; 8 warps (2m x 4n).
// grid (16 s, 10 o, 8 b) = 1280 CTAs, 256 thr.
// ============================================================================
static constexpr int U_HT = 64 * LDP;
static constexpr int U_WT = 128 * LDP;
static constexpr int SMEM_UP = (2 * U_HT + 2 * U_WT) * 2;  // 55296 B

__global__ __launch_bounds__(256)
void k_up(float* __restrict__ out) {
    extern __shared__ __nv_bfloat16 sm[];
    __nv_bfloat16* HH = sm;
    __nv_bfloat16* HL = sm + U_HT;
    const uint32_t smb = smem_u32(sm);

    const int tid = threadIdx.x, lane = tid & 31, wid = tid >> 5;
    const int b = blockIdx.z, s0 = blockIdx.x * 64, o0 = blockIdx.y * 128;
    const float* __restrict__ h0p = g_hp[0] + ((size_t)b * SQ + s0) * RNK;
    const float* __restrict__ h1p = g_hp[1] + ((size_t)b * SQ + s0) * RNK;
    const __nv_bfloat16* __restrict__ weh = g_eh + (size_t)b * EMBSZ + DOWNSZ + (size_t)o0 * RNK;
    const __nv_bfloat16* __restrict__ wel = g_el + (size_t)b * EMBSZ + DOWNSZ + (size_t)o0 * RNK;

    // W fill via cp.async: 128 rows x 64 cols, hi+lo
    {
        const int wrow = tid >> 3, c8 = (tid & 7) * 8;
        const uint32_t WHb = smb + 4 * U_HT, WLb = smb + 4 * U_HT + 2 * U_WT;
#pragma unroll
        for (int p = 0; p < 4; p++) {
            const int row = wrow + p * 32;
            cpa16(WHb + (uint32_t)(row * LDP + c8) * 2, weh + (size_t)row * RNK + c8);
            cpa16(WLb + (uint32_t)(row * LDP + c8) * 2, wel + (size_t)row * RNK + c8);
        }
        CP_COMMIT;
    }
    // h fill: sum split-K partials + split (overlaps the cp.asyncs)
    {
        const int frow = tid >> 4, fcol = (tid & 15) * 4;
#pragma unroll
        for (int p = 0; p < 4; p++) {
            const int row = p * 16 + frow;
            float4 a = *(const float4*)(h0p + (size_t)row * RNK + fcol);
            float4 c = *(const float4*)(h1p + (size_t)row * RNK + fcol);
            uint32_t h0, l0, h1, l1;
            split2f(a.x + c.x, a.y + c.y, h0, l0);
            split2f(a.z + c.z, a.w + c.w, h1, l1);
            *(uint2*)(HH + row * LDP + fcol) = make_uint2(h0, h1);
            *(uint2*)(HL + row * LDP + fcol) = make_uint2(l0, l1);
        }
    }
    CP_WAIT0;
    __syncthreads();

    const int wm = wid >> 2, wn = wid & 3;
    const int m0 = wm * 32, n0 = wn * 32;
    const int r8 = lane & 7, gq = lane >> 3;

    const uint32_t HHa = smb, HLa = smb + U_HT * 2;
    const uint32_t WHa = smb + 4 * U_HT, WLa = smb + 4 * U_HT + 2 * U_WT;
    const uint32_t offA0 = (uint32_t)(m0 + r8 + (gq & 1) * 8) * LDPB + (gq >> 1) * 16;
    const uint32_t offA1 = offA0 + 16 * LDPB;
    const uint32_t offB0 = (uint32_t)(n0 + r8 + (gq >> 1) * 8) * LDPB + (gq & 1) * 16;
    const uint32_t offB2 = offB0 + 16 * LDPB;

    float acc[2][4][4];
#pragma unroll
    for (int t = 0; t < 2; t++)
#pragma unroll
        for (int u = 0; u < 4; u++)
#pragma unroll
            for (int j = 0; j < 4; j++) acc[t][u][j] = 0.f;

#pragma unroll
    for (int kk = 0; kk < 4; kk++) {
        const uint32_t ko = kk * 32;
        uint32_t aH0[4], aL0[4], aH1[4], aL1[4];
        uint32_t bH[4], bL[4], bH2[4], bL2[4];
        LDSM4(aH0, HHa + offA0 + ko);
        LDSM4(aL0, HLa + offA0 + ko);
        LDSM4(aH1, HHa + offA1 + ko);
        LDSM4(aL1, HLa + offA1 + ko);
        LDSM4(bH, WHa + offB0 + ko);
        LDSM4(bL, WLa + offB0 + ko);
        LDSM4(bH2, WHa + offB2 + ko);
        LDSM4(bL2, WLa + offB2 + ko);
#pragma unroll
        for (int t = 0; t < 2; t++) {
            const uint32_t* aH = t ? aH1 : aH0;
            const uint32_t* aL = t ? aL1 : aL0;
            mma16816(acc[t][0], aH, bH);      mma16816(acc[t][0], aH, bL);      mma16816(acc[t][0], aL, bH);
            mma16816(acc[t][1], aH, bH + 2);  mma16816(acc[t][1], aH, bL + 2);  mma16816(acc[t][1], aL, bH + 2);
            mma16816(acc[t][2], aH, bH2);     mma16816(acc[t][2], aH, bL2);     mma16816(acc[t][2], aL, bH2);
            mma16816(acc[t][3], aH, bH2 + 2); mma16816(acc[t][3], aH, bL2 + 2); mma16816(acc[t][3], aL, bH2 + 2);
        }
    }

    const int g = lane >> 2, tg = lane & 3;
#pragma unroll
    for (int t = 0; t < 2; t++) {
        const size_t r0 = (size_t)b * SQ + s0 + m0 + t * 16 + g;
#pragma unroll
        for (int u = 0; u < 4; u++) {
            const int c = o0 + n0 + u * 8 + tg * 2;
            *(float2*)(out + r0 * DOUT + c)       = make_float2(acc[t][u][0], acc[t][u][1]);
            *(float2*)(out + (r0 + 8) * DOUT + c) = make_float2(acc[t][u][2], acc[t][u][3]);
        }
    }
}

extern "C" void kernel_launch(void* const* d_in, const int* in_sizes, int n_in,
                              void* d_out, int out_size) {
    const float* x     = (const float*)d_in[0];   // [8,1024,1280]
    const float* embed = (const float*)d_in[1];   // [8,163840]
    float*       out   = (float*)d_out;           // [8,1024,1280]
    (void)in_sizes; (void)n_in; (void)out_size;

    cudaFuncSetAttribute(k_down, cudaFuncAttributeMaxDynamicSharedMemorySize, SMEM_DOWN);
    cudaFuncSetAttribute(k_up,   cudaFuncAttributeMaxDynamicSharedMemorySize, SMEM_UP);

    k_prep<<<NB * EMBSZ / (256 * 16), 256>>>(embed);   // 320 blocks
    k_down<<<dim3(16, 2, 8), 256, SMEM_DOWN>>>(x);
    k_up<<<dim3(16, 10, 8), 256, SMEM_UP>>>(out);
}